// round 12
// baseline (speedup 1.0000x reference)
#include <cuda_runtime.h>
#include <cuda_fp16.h>
#include <cstdint>
#include <cstddef>

#define MT   16384      // B*S rows
#define K1   1536       // 2*C
#define NN   256
#define C_   768
#define HW_  3136

// ---------------------------------------------------------------------------
// Device scratch (allocation-free)
// ---------------------------------------------------------------------------
static __device__ __align__(128) __half g_w1[(size_t)NN * K1];   // W1^T fp16
static __device__ __align__(128) __half g_w2[(size_t)NN * NN];   // W2^T fp16
static __device__ __align__(128) __half g_h1[(size_t)MT * NN];   // h1 fp16 row-major

// ---------------------------------------------------------------------------
// Helpers
// ---------------------------------------------------------------------------
__device__ __forceinline__ uint32_t s2u(const void* p) {
    uint32_t a;
    asm("{ .reg .u64 t; cvta.to.shared.u64 t, %1; cvt.u32.u64 %0, t; }" : "=r"(a) : "l"(p));
    return a;
}
__device__ __forceinline__ void cpasync16(uint32_t dst, const void* src) {
    asm volatile("cp.async.cg.shared.global [%0], [%1], 16;" :: "r"(dst), "l"(src));
}
__device__ __forceinline__ void cp_commit() { asm volatile("cp.async.commit_group;"); }
template <int N>
__device__ __forceinline__ void cp_wait() { asm volatile("cp.async.wait_group %0;" :: "n"(N)); }

__device__ __forceinline__ void ldsm4(uint32_t& r0, uint32_t& r1, uint32_t& r2, uint32_t& r3,
                                      uint32_t addr) {
    asm volatile("ldmatrix.sync.aligned.m8n8.x4.shared.b16 {%0,%1,%2,%3}, [%4];"
                 : "=r"(r0), "=r"(r1), "=r"(r2), "=r"(r3) : "r"(addr));
}
__device__ __forceinline__ void mma16816(float* c, const uint32_t* a, const uint32_t* b) {
    asm volatile(
        "mma.sync.aligned.m16n8k16.row.col.f32.f16.f16.f32 "
        "{%0,%1,%2,%3}, {%4,%5,%6,%7}, {%8,%9}, {%0,%1,%2,%3};"
        : "+f"(c[0]), "+f"(c[1]), "+f"(c[2]), "+f"(c[3])
        : "r"(a[0]), "r"(a[1]), "r"(a[2]), "r"(a[3]), "r"(b[0]), "r"(b[1]));
}
__device__ __forceinline__ uint32_t pack_h2(float v0, float v1) {
    __half2 t = __floats2half2_rn(v0, v1);
    return *(uint32_t*)&t;
}

// Weight transpose: W[K,256] fp32 -> Wt[256][K] fp16
__global__ void wtrans(const float* __restrict__ W, int K,
                       __half* __restrict__ wt) {
    int t = blockIdx.x * blockDim.x + threadIdx.x;
    if (t >= K * NN) return;
    int n = t / K, k = t % K;
    wt[(size_t)n * K + k] = __float2half(W[(size_t)k * NN + n]);
}

// ---------------------------------------------------------------------------
// FUSED gather + GEMM1: h1[m,0:256] = relu(gather(x)[m,0:1536] @ W1 + b1)
// Grid 128 CTAs (M tiles of 128), 512 threads (16 warps, 4x4, warp tile 32x64).
// A gathered from x per stage: 16 LDG/thread into regs (issued before the
// previous stage's MMA section -> latency hidden), convert+STS after.
// B (w1) via 2-stage cp.async double buffer. deltaxy computed in prologue.
// ---------------------------------------------------------------------------
__global__ void __launch_bounds__(512, 1)
gemm1_fused(const float* __restrict__ x,
            const int* __restrict__ pxs, const int* __restrict__ pys,
            const __half* __restrict__ Bw, const float* __restrict__ bias,
            __half* __restrict__ O, float* __restrict__ delta_out) {
    constexpr int BK   = 64;
    constexpr int ROWB = 144;                    // padded smem row stride
    constexpr int ASTG = 128 * ROWB;             // 18432 B per A stage
    constexpr int BBASE = 2 * ASTG;
    constexpr int BSTG = 256 * ROWB;             // 36864 B per B stage
    constexpr int MI = 2;                        // WM=32 -> 2 m16 frags
    constexpr int NJ = 4;                        // WN=64 -> 4 n16 frags
    constexpr int NK = K1 / BK;                  // 24

    extern __shared__ char dsm[];
    __shared__ int offs[128][2];

    const int tid  = threadIdx.x;
    const int lane = tid & 31;
    const int wid  = tid >> 5;
    const int wm   = wid >> 2;       // 0..3
    const int wn   = wid & 3;        // 0..3
    const int m0   = blockIdx.x * 128;

    // prologue: per-row gather offsets + deltaxy
    if (tid < 128) {
        int row = m0 + tid;
        int b   = row >> 8;
        int px0 = pxs[row * 2], px1 = pxs[row * 2 + 1];
        int py0 = pys[row * 2], py1 = pys[row * 2 + 1];
        delta_out[row * 2 + 0] = (float)(px0 - py0) + 55.0f;
        delta_out[row * 2 + 1] = (float)(px1 - py1) + 55.0f;
        offs[tid][0] = b * (C_ * HW_) + px0 * 56 + px1;
        offs[tid][1] = b * (C_ * HW_) + py0 * 56 + py1;
    }
    __syncthreads();

    const uint32_t sbase = s2u(dsm);
    // ldmatrix per-lane offsets (relative within a stage buffer)
    const uint32_t aoff = (uint32_t)((wm * 32 + (lane & 15)) * ROWB + ((lane & 16) ? 16 : 0));
    const uint32_t boff = (uint32_t)((wn * 64 + (lane & 7) + ((lane & 16) ? 8 : 0)) * ROWB
                                     + ((lane & 8) ? 16 : 0));

    // gather thread mapping: 4 threads per row, 16 channels each
    const int g_row = tid >> 2;          // 0..127
    const int g_kc  = (tid & 3) * 16;    // 0,16,32,48

    float areg[16];
    auto ldg_A = [&](int kt) {
        int k0   = kt * BK;
        int side = (k0 >= C_) ? 1 : 0;
        int cb   = k0 - side * C_ + g_kc;
        const float* p = x + offs[g_row][side] + (size_t)cb * HW_;
        #pragma unroll
        for (int i = 0; i < 16; i++) areg[i] = __ldg(p + (size_t)i * HW_);
    };
    auto sts_A = [&](int buf) {
        uint32_t dst = sbase + buf * ASTG + (uint32_t)(g_row * ROWB + g_kc * 2);
        #pragma unroll
        for (int i = 0; i < 8; i++) {
            uint32_t h2 = pack_h2(areg[2 * i], areg[2 * i + 1]);
            asm volatile("st.shared.b32 [%0], %1;" :: "r"(dst + i * 4), "r"(h2));
        }
    };
    auto load_B = [&](int buf, int kt) {
        const uint32_t sd = sbase + BBASE + buf * BSTG;
        const int k0 = kt * BK;
        #pragma unroll
        for (int c = tid; c < 256 * 8; c += 512) {
            int row = c >> 3, kc = c & 7;
            cpasync16(sd + (uint32_t)(row * ROWB + kc * 16),
                      Bw + (size_t)row * K1 + k0 + kc * 8);
        }
        cp_commit();
    };

    float acc[MI][2 * NJ][4];
    #pragma unroll
    for (int i = 0; i < MI; i++)
        #pragma unroll
        for (int j = 0; j < 2 * NJ; j++)
            #pragma unroll
            for (int q = 0; q < 4; q++) acc[i][j][q] = 0.0f;

    // stage 0
    ldg_A(0);
    load_B(0, 0);
    sts_A(0);

    for (int kt = 0; kt < NK; kt++) {
        int cur = kt & 1;
        if (kt + 1 < NK) { ldg_A(kt + 1); load_B(cur ^ 1, kt + 1); cp_wait<1>(); }
        else             { cp_wait<0>(); }
        __syncthreads();    // A(kt) STS + B(kt) visible

        const uint32_t sa = sbase + cur * ASTG;
        const uint32_t sb = sbase + BBASE + cur * BSTG;
        #pragma unroll
        for (int kk = 0; kk < BK / 16; kk++) {
            uint32_t a[MI][4], b[NJ][4];
            #pragma unroll
            for (int i = 0; i < MI; i++) {
                uint32_t ad = sa + aoff + i * 16 * ROWB + kk * 32;
                ldsm4(a[i][0], a[i][1], a[i][2], a[i][3], ad);
            }
            #pragma unroll
            for (int j = 0; j < NJ; j++) {
                uint32_t bd = sb + boff + j * 16 * ROWB + kk * 32;
                ldsm4(b[j][0], b[j][1], b[j][2], b[j][3], bd);
            }
            #pragma unroll
            for (int i = 0; i < MI; i++)
                #pragma unroll
                for (int j = 0; j < NJ; j++) {
                    mma16816(acc[i][2 * j + 0], a[i], &b[j][0]);
                    mma16816(acc[i][2 * j + 1], a[i], &b[j][2]);
                }
        }
        __syncthreads();    // compute(kt) done before next stage overwrites
        if (kt + 1 < NK) sts_A(cur ^ 1);
    }

    // epilogue: h1 = fp16(relu(acc + b1))
    const int qr = lane >> 2;
    const int qc = lane & 3;
    #pragma unroll
    for (int i = 0; i < MI; i++) {
        #pragma unroll
        for (int j = 0; j < 2 * NJ; j++) {
            int n = wn * 64 + j * 8 + 2 * qc;
            float bz0 = __ldg(bias + n), bz1 = __ldg(bias + n + 1);
            int mA = m0 + wm * 32 + i * 16 + qr;
            float v00 = fmaxf(acc[i][j][0] + bz0, 0.0f);
            float v01 = fmaxf(acc[i][j][1] + bz1, 0.0f);
            float v10 = fmaxf(acc[i][j][2] + bz0, 0.0f);
            float v11 = fmaxf(acc[i][j][3] + bz1, 0.0f);
            *(uint32_t*)&O[(size_t)mA * NN + n]       = pack_h2(v00, v01);
            *(uint32_t*)&O[(size_t)(mA + 8) * NN + n] = pack_h2(v10, v11);
        }
    }
}

// ---------------------------------------------------------------------------
// GEMM2 (+fused GEMM3): proven round-10 kernel, EPI=1 path.
// ---------------------------------------------------------------------------
template <int BN, int NWM, int NWN, int WM, int WN, int OCC>
__global__ void __launch_bounds__(NWM * NWN * 32, OCC)
gemm2_mma(const __half* __restrict__ A, const __half* __restrict__ B,
          const float* __restrict__ bias, int K,
          const float* __restrict__ W3, const float* __restrict__ b3,
          float* __restrict__ Out) {
    constexpr int BK = 64;
    constexpr int ROWB = 144;
    constexpr int ABASE = 0;
    constexpr int BB = 128 * ROWB;
    constexpr int STG = BB + BN * ROWB;
    constexpr int NTHR = NWM * NWN * 32;
    constexpr int MI = WM / 16;
    constexpr int NJ = WN / 16;

    extern __shared__ char dsm[];
    __shared__ float red[128][2];

    const int tid  = threadIdx.x;
    const int lane = tid & 31;
    const int wid  = tid >> 5;
    const int wm   = wid / NWN;
    const int wn   = wid % NWN;
    const int m0   = blockIdx.x * 128;

    if (tid < 256) red[tid >> 1][tid & 1] = 0.0f;

    const uint32_t sbase = s2u(dsm);
    const uint32_t aoff = (uint32_t)((wm * WM + (lane & 15)) * ROWB + ((lane & 16) ? 16 : 0));
    const uint32_t boff = (uint32_t)(BB + (wn * WN + (lane & 7) + ((lane & 16) ? 8 : 0)) * ROWB
                                     + ((lane & 8) ? 16 : 0));

    float acc[MI][2 * NJ][4];
    #pragma unroll
    for (int i = 0; i < MI; i++)
        #pragma unroll
        for (int j = 0; j < 2 * NJ; j++)
            #pragma unroll
            for (int q = 0; q < 4; q++) acc[i][j][q] = 0.0f;

    const int NK = K / BK;

    auto load_stage = [&](int buf, int kt) {
        const uint32_t sd = sbase + buf * STG;
        const int k0 = kt * BK;
        constexpr int CHUNKS = (128 + BN) * 8;
        #pragma unroll
        for (int c = tid; c < CHUNKS; c += NTHR) {
            int row = c >> 3, kc = c & 7, kb = kc * 16;
            const __half* src;
            uint32_t dst;
            if (row < 128) {
                src = A + (size_t)(m0 + row) * K + k0 + kc * 8;
                dst = sd + ABASE + row * ROWB + kb;
            } else {
                int r = row - 128;
                src = B + (size_t)r * K + k0 + kc * 8;
                dst = sd + BB + r * ROWB + kb;
            }
            cpasync16(dst, src);
        }
        cp_commit();
    };

    load_stage(0, 0);

    for (int kt = 0; kt < NK; kt++) {
        if (kt + 1 < NK) { load_stage((kt + 1) & 1, kt + 1); cp_wait<1>(); }
        else             { cp_wait<0>(); }
        __syncthreads();

        const uint32_t sd = sbase + (kt & 1) * STG;
        #pragma unroll
        for (int kk = 0; kk < BK / 16; kk++) {
            uint32_t a[MI][4], b[NJ][4];
            #pragma unroll
            for (int i = 0; i < MI; i++) {
                uint32_t ad = sd + aoff + i * 16 * ROWB + kk * 32;
                ldsm4(a[i][0], a[i][1], a[i][2], a[i][3], ad);
            }
            #pragma unroll
            for (int j = 0; j < NJ; j++) {
                uint32_t bd = sd + boff + j * 16 * ROWB + kk * 32;
                ldsm4(b[j][0], b[j][1], b[j][2], b[j][3], bd);
            }
            #pragma unroll
            for (int i = 0; i < MI; i++)
                #pragma unroll
                for (int j = 0; j < NJ; j++) {
                    mma16816(acc[i][2 * j + 0], a[i], &b[j][0]);
                    mma16816(acc[i][2 * j + 1], a[i], &b[j][2]);
                }
        }
        __syncthreads();
    }

    const int qr = lane >> 2;
    const int qc = lane & 3;
    float s[MI][2][2];
    #pragma unroll
    for (int i = 0; i < MI; i++)
        s[i][0][0] = s[i][0][1] = s[i][1][0] = s[i][1][1] = 0.0f;
    #pragma unroll
    for (int i = 0; i < MI; i++) {
        #pragma unroll
        for (int j = 0; j < 2 * NJ; j++) {
            int n = wn * WN + j * 8 + 2 * qc;
            float bz0 = __ldg(bias + n), bz1 = __ldg(bias + n + 1);
            float w00 = __ldg(W3 + n * 2),     w01 = __ldg(W3 + n * 2 + 1);
            float w10 = __ldg(W3 + n * 2 + 2), w11 = __ldg(W3 + n * 2 + 3);
            float v00 = fmaxf(acc[i][j][0] + bz0, 0.0f);
            float v01 = fmaxf(acc[i][j][1] + bz1, 0.0f);
            float v10 = fmaxf(acc[i][j][2] + bz0, 0.0f);
            float v11 = fmaxf(acc[i][j][3] + bz1, 0.0f);
            s[i][0][0] += v00 * w00 + v01 * w10;
            s[i][0][1] += v00 * w01 + v01 * w11;
            s[i][1][0] += v10 * w00 + v11 * w10;
            s[i][1][1] += v10 * w01 + v11 * w11;
        }
    }
    #pragma unroll
    for (int i = 0; i < MI; i++)
        #pragma unroll
        for (int r = 0; r < 2; r++)
            #pragma unroll
            for (int o = 0; o < 2; o++) {
                float v = s[i][r][o];
                v += __shfl_xor_sync(0xffffffffu, v, 1);
                v += __shfl_xor_sync(0xffffffffu, v, 2);
                s[i][r][o] = v;
            }
    if (qc == 0) {
        #pragma unroll
        for (int i = 0; i < MI; i++)
            #pragma unroll
            for (int r = 0; r < 2; r++) {
                int mrow = wm * WM + i * 16 + r * 8 + qr;
                atomicAdd(&red[mrow][0], s[i][r][0]);
                atomicAdd(&red[mrow][1], s[i][r][1]);
            }
    }
    __syncthreads();
    if (tid < 256) {
        int m = tid >> 1, o = tid & 1;
        Out[(size_t)(m0 + m) * 2 + o] = red[m][o] + __ldg(b3 + o);
    }
}

// ---------------------------------------------------------------------------
extern "C" void kernel_launch(void* const* d_in, const int* in_sizes, int n_in,
                              void* d_out, int out_size) {
    const float* x   = (const float*)d_in[0];
    const int*   pxs = (const int*)d_in[1];
    const int*   pys = (const int*)d_in[2];
    const float* W1  = (const float*)d_in[3];
    const float* b1  = (const float*)d_in[4];
    const float* W2  = (const float*)d_in[5];
    const float* b2  = (const float*)d_in[6];
    const float* W3  = (const float*)d_in[7];
    const float* b3  = (const float*)d_in[8];
    float* out = (float*)d_out;

    __half *w1, *w2, *h1;
    cudaGetSymbolAddress((void**)&w1, g_w1);
    cudaGetSymbolAddress((void**)&w2, g_w2);
    cudaGetSymbolAddress((void**)&h1, g_h1);

    auto k2f = gemm2_mma<256, 4, 4, 32, 64, 1>;
    const int SM1 = 2 * (128 * 144) + 2 * (256 * 144);   // 110592
    const int SM2 = 2 * ((128 + 256) * 144);             // 110592
    cudaFuncSetAttribute(gemm1_fused, cudaFuncAttributeMaxDynamicSharedMemorySize, SM1);
    cudaFuncSetAttribute(k2f, cudaFuncAttributeMaxDynamicSharedMemorySize, SM2);

    int half = out_size / 2;

    wtrans<<<(K1 * NN) / 256, 256>>>(W1, K1, w1);
    wtrans<<<(NN * NN) / 256, 256>>>(W2, NN, w2);
    gemm1_fused<<<MT / 128, 512, SM1>>>(x, pxs, pys, w1, b1, h1, out + half);
    k2f<<<dim3(MT / 128, 1), 512, SM2>>>(h1, w2, b2, NN, W3, b3, out);
}

// round 14
// speedup vs baseline: 1.2500x; 1.2500x over previous
#include <cuda_runtime.h>
#include <cuda_fp16.h>
#include <cstdint>
#include <cstddef>

#define MT   16384      // B*S rows
#define K1   1536       // 2*C
#define NN   256
#define C_   768
#define HW_  3136

// ---------------------------------------------------------------------------
// Device scratch (allocation-free)
// ---------------------------------------------------------------------------
static __device__ __align__(128) __half g_fa[(size_t)MT * K1];   // feats fp16
static __device__ __align__(128) __half g_w1[(size_t)NN * K1];   // W1^T fp16
static __device__ __align__(128) __half g_w2[(size_t)NN * NN];   // W2^T fp16
static __device__ __align__(128) __half g_h1[(size_t)MT * NN];   // h1 fp16 row-major

// ---------------------------------------------------------------------------
// Helpers
// ---------------------------------------------------------------------------
__device__ __forceinline__ uint32_t s2u(const void* p) {
    uint32_t a;
    asm("{ .reg .u64 t; cvta.to.shared.u64 t, %1; cvt.u32.u64 %0, t; }" : "=r"(a) : "l"(p));
    return a;
}
__device__ __forceinline__ void cpasync16(uint32_t dst, const void* src) {
    asm volatile("cp.async.cg.shared.global [%0], [%1], 16;" :: "r"(dst), "l"(src));
}
__device__ __forceinline__ void cp_commit() { asm volatile("cp.async.commit_group;"); }
template <int N>
__device__ __forceinline__ void cp_wait() { asm volatile("cp.async.wait_group %0;" :: "n"(N)); }

__device__ __forceinline__ void ldsm4(uint32_t& r0, uint32_t& r1, uint32_t& r2, uint32_t& r3,
                                      uint32_t addr) {
    asm volatile("ldmatrix.sync.aligned.m8n8.x4.shared.b16 {%0,%1,%2,%3}, [%4];"
                 : "=r"(r0), "=r"(r1), "=r"(r2), "=r"(r3) : "r"(addr));
}
__device__ __forceinline__ void mma16816(float* c, const uint32_t* a, const uint32_t* b) {
    asm volatile(
        "mma.sync.aligned.m16n8k16.row.col.f32.f16.f16.f32 "
        "{%0,%1,%2,%3}, {%4,%5,%6,%7}, {%8,%9}, {%0,%1,%2,%3};"
        : "+f"(c[0]), "+f"(c[1]), "+f"(c[2]), "+f"(c[3])
        : "r"(a[0]), "r"(a[1]), "r"(a[2]), "r"(a[3]), "r"(b[0]), "r"(b[1]));
}
__device__ __forceinline__ uint32_t pack_h2(float v0, float v1) {
    __half2 t = __floats2half2_rn(v0, v1);
    return *(uint32_t*)&t;
}

// ---------------------------------------------------------------------------
// Gather -> fp16 feats (+ fused deltaxy). 256 threads, fully unrolled:
// each thread issues 6 independent LDGs (3 channels x 2 points) -> MLP=6.
// ---------------------------------------------------------------------------
__global__ void __launch_bounds__(256)
gather_fp16(const float* __restrict__ x,
            const int* __restrict__ pxs,
            const int* __restrict__ pys,
            float* __restrict__ delta_out) {
    int row = blockIdx.x;
    int b   = row >> 8;
    int px0 = pxs[row * 2], px1 = pxs[row * 2 + 1];
    int py0 = pys[row * 2], py1 = pys[row * 2 + 1];
    if (threadIdx.x == 0) {
        delta_out[row * 2 + 0] = (float)(px0 - py0) + 55.0f;
        delta_out[row * 2 + 1] = (float)(px1 - py1) + 55.0f;
    }
    const float* xb = x + (size_t)b * (C_ * HW_);
    const float* pX = xb + (px0 * 56 + px1);
    const float* pY = xb + (py0 * 56 + py1);
    int c = threadIdx.x;

    // 6 independent loads in flight
    float a0 = __ldg(pX + (size_t)c * HW_);
    float a1 = __ldg(pX + (size_t)(c + 256) * HW_);
    float a2 = __ldg(pX + (size_t)(c + 512) * HW_);
    float b0 = __ldg(pY + (size_t)c * HW_);
    float b1 = __ldg(pY + (size_t)(c + 256) * HW_);
    float b2 = __ldg(pY + (size_t)(c + 512) * HW_);

    __half* fr = g_fa + (size_t)row * K1;
    fr[c]            = __float2half(a0);
    fr[c + 256]      = __float2half(a1);
    fr[c + 512]      = __float2half(a2);
    fr[C_ + c]       = __float2half(b0);
    fr[C_ + c + 256] = __float2half(b1);
    fr[C_ + c + 512] = __float2half(b2);
}

// Weight transpose: W[K,256] fp32 -> Wt[256][K] fp16
__global__ void wtrans(const float* __restrict__ W, int K,
                       __half* __restrict__ wt) {
    int t = blockIdx.x * blockDim.x + threadIdx.x;
    if (t >= K * NN) return;
    int n = t / K, k = t % K;
    wt[(size_t)n * K + k] = __float2half(W[(size_t)k * NN + n]);
}

// ---------------------------------------------------------------------------
// mma.sync GEMM. A[M,K](fp16) @ Wt[BNtot,K]^T (fp16), fp32 acc, single term.
// BK=64, 2-stage cp.async double buffer; smem rows padded to 144B.
// EPI=0: O = fp16(relu(D+bias)) row-major (n range [bn0, bn0+BN)).
// EPI=1: Out[m,0:2] = relu(D+bias) @ W3 + b3 (full N=256 in one CTA).
// ---------------------------------------------------------------------------
template <int BN, int NWM, int NWN, int WM, int WN, int EPI, int OCC>
__global__ void __launch_bounds__(NWM * NWN * 32, OCC)
gemm_mma(const __half* __restrict__ A, const __half* __restrict__ B,
         const float* __restrict__ bias, int K,
         __half* __restrict__ O,
         const float* __restrict__ W3, const float* __restrict__ b3,
         float* __restrict__ Out) {
    constexpr int BK = 64;
    constexpr int ROWB = 144;               // padded smem row stride (bytes)
    constexpr int ABASE = 0;
    constexpr int BB = 128 * ROWB;
    constexpr int STG = BB + BN * ROWB;
    constexpr int NTHR = NWM * NWN * 32;
    constexpr int MI = WM / 16;
    constexpr int NJ = WN / 16;

    extern __shared__ char dsm[];
    __shared__ float red[128][2];

    const int tid  = threadIdx.x;
    const int lane = tid & 31;
    const int wid  = tid >> 5;
    const int wm   = wid / NWN;
    const int wn   = wid % NWN;
    const int m0   = blockIdx.x * 128;
    const int bn0  = blockIdx.y * BN;

    if (EPI == 1 && tid < 256) red[tid >> 1][tid & 1] = 0.0f;

    const uint32_t sbase = s2u(dsm);
    const int a_row = wm * WM + (lane & 15);
    const int a_kb  = (lane & 16) ? 16 : 0;
    const uint32_t aoff = (uint32_t)(ABASE + a_row * ROWB + a_kb);
    const int b_row = wn * WN + (lane & 7) + ((lane & 16) ? 8 : 0);
    const int b_kb  = (lane & 8) ? 16 : 0;
    const uint32_t boff = (uint32_t)(BB + b_row * ROWB + b_kb);

    float acc[MI][2 * NJ][4];
    #pragma unroll
    for (int i = 0; i < MI; i++)
        #pragma unroll
        for (int j = 0; j < 2 * NJ; j++)
            #pragma unroll
            for (int q = 0; q < 4; q++) acc[i][j][q] = 0.0f;

    const int NK = K / BK;

    auto load_stage = [&](int buf, int kt) {
        const uint32_t sd = sbase + buf * STG;
        const int k0 = kt * BK;
        constexpr int CHUNKS = (128 + BN) * 8;   // 16B chunks
        #pragma unroll
        for (int c = tid; c < CHUNKS; c += NTHR) {
            int row = c >> 3;
            int kc  = (c & 7);
            int kb  = kc * 16;
            const __half* src;
            uint32_t dst;
            if (row < 128) {
                src = A + (size_t)(m0 + row) * K + k0 + kc * 8;
                dst = sd + ABASE + row * ROWB + kb;
            } else {
                int r = row - 128;
                src = B + (size_t)(bn0 + r) * K + k0 + kc * 8;
                dst = sd + BB + r * ROWB + kb;
            }
            cpasync16(dst, src);
        }
        cp_commit();
    };

    load_stage(0, 0);

    for (int kt = 0; kt < NK; kt++) {
        if (kt + 1 < NK) { load_stage((kt + 1) & 1, kt + 1); cp_wait<1>(); }
        else             { cp_wait<0>(); }
        __syncthreads();

        const uint32_t sd = sbase + (kt & 1) * STG;
        #pragma unroll
        for (int kk = 0; kk < BK / 16; kk++) {
            uint32_t a[MI][4], b[NJ][4];
            #pragma unroll
            for (int i = 0; i < MI; i++) {
                uint32_t ad = sd + aoff + i * 16 * ROWB + kk * 32;
                ldsm4(a[i][0], a[i][1], a[i][2], a[i][3], ad);
            }
            #pragma unroll
            for (int j = 0; j < NJ; j++) {
                uint32_t bd = sd + boff + j * 16 * ROWB + kk * 32;
                ldsm4(b[j][0], b[j][1], b[j][2], b[j][3], bd);
            }
            #pragma unroll
            for (int i = 0; i < MI; i++)
                #pragma unroll
                for (int j = 0; j < NJ; j++) {
                    mma16816(acc[i][2 * j + 0], a[i], &b[j][0]);
                    mma16816(acc[i][2 * j + 1], a[i], &b[j][2]);
                }
        }
        __syncthreads();
    }

    // ---- epilogue ----
    const int qr = lane >> 2;
    const int qc = lane & 3;
    if (EPI == 0) {
        #pragma unroll
        for (int i = 0; i < MI; i++) {
            #pragma unroll
            for (int j = 0; j < 2 * NJ; j++) {
                int n = bn0 + wn * WN + j * 8 + 2 * qc;
                float bz0 = __ldg(bias + n), bz1 = __ldg(bias + n + 1);
                int mA = m0 + wm * WM + i * 16 + qr;
                float v00 = fmaxf(acc[i][j][0] + bz0, 0.0f);
                float v01 = fmaxf(acc[i][j][1] + bz1, 0.0f);
                float v10 = fmaxf(acc[i][j][2] + bz0, 0.0f);
                float v11 = fmaxf(acc[i][j][3] + bz1, 0.0f);
                *(uint32_t*)&O[(size_t)mA * NN + n]       = pack_h2(v00, v01);
                *(uint32_t*)&O[(size_t)(mA + 8) * NN + n] = pack_h2(v10, v11);
            }
        }
    } else {
        float s[MI][2][2];
        #pragma unroll
        for (int i = 0; i < MI; i++)
            s[i][0][0] = s[i][0][1] = s[i][1][0] = s[i][1][1] = 0.0f;
        #pragma unroll
        for (int i = 0; i < MI; i++) {
            #pragma unroll
            for (int j = 0; j < 2 * NJ; j++) {
                int n = wn * WN + j * 8 + 2 * qc;
                float bz0 = __ldg(bias + n), bz1 = __ldg(bias + n + 1);
                float w00 = __ldg(W3 + n * 2),     w01 = __ldg(W3 + n * 2 + 1);
                float w10 = __ldg(W3 + n * 2 + 2), w11 = __ldg(W3 + n * 2 + 3);
                float v00 = fmaxf(acc[i][j][0] + bz0, 0.0f);
                float v01 = fmaxf(acc[i][j][1] + bz1, 0.0f);
                float v10 = fmaxf(acc[i][j][2] + bz0, 0.0f);
                float v11 = fmaxf(acc[i][j][3] + bz1, 0.0f);
                s[i][0][0] += v00 * w00 + v01 * w10;
                s[i][0][1] += v00 * w01 + v01 * w11;
                s[i][1][0] += v10 * w00 + v11 * w10;
                s[i][1][1] += v10 * w01 + v11 * w11;
            }
        }
        #pragma unroll
        for (int i = 0; i < MI; i++)
            #pragma unroll
            for (int r = 0; r < 2; r++)
                #pragma unroll
                for (int o = 0; o < 2; o++) {
                    float v = s[i][r][o];
                    v += __shfl_xor_sync(0xffffffffu, v, 1);
                    v += __shfl_xor_sync(0xffffffffu, v, 2);
                    s[i][r][o] = v;
                }
        if (qc == 0) {
            #pragma unroll
            for (int i = 0; i < MI; i++)
                #pragma unroll
                for (int r = 0; r < 2; r++) {
                    int mrow = wm * WM + i * 16 + r * 8 + qr;
                    atomicAdd(&red[mrow][0], s[i][r][0]);
                    atomicAdd(&red[mrow][1], s[i][r][1]);
                }
        }
        __syncthreads();
        if (tid < 256) {
            int m = tid >> 1, o = tid & 1;
            Out[(size_t)(m0 + m) * 2 + o] = red[m][o] + __ldg(b3 + o);
        }
    }
}

// ---------------------------------------------------------------------------
extern "C" void kernel_launch(void* const* d_in, const int* in_sizes, int n_in,
                              void* d_out, int out_size) {
    const float* x   = (const float*)d_in[0];
    const int*   pxs = (const int*)d_in[1];
    const int*   pys = (const int*)d_in[2];
    const float* W1  = (const float*)d_in[3];
    const float* b1  = (const float*)d_in[4];
    const float* W2  = (const float*)d_in[5];
    const float* b2  = (const float*)d_in[6];
    const float* W3  = (const float*)d_in[7];
    const float* b3  = (const float*)d_in[8];
    float* out = (float*)d_out;

    __half *fa, *w1, *w2, *h1;
    cudaGetSymbolAddress((void**)&fa, g_fa);
    cudaGetSymbolAddress((void**)&w1, g_w1);
    cudaGetSymbolAddress((void**)&w2, g_w2);
    cudaGetSymbolAddress((void**)&h1, g_h1);

    // GEMM1: BN=128, 8 warps (2x4), warp tile 64x32, 2 CTAs/SM.
    auto k1f = gemm_mma<128, 2, 4, 64, 32, 0, 2>;
    // GEMM2: BN=256, 16 warps (4x4), warp tile 32x64, fused GEMM3.
    auto k2f = gemm_mma<256, 4, 4, 32, 64, 1, 1>;
    const int SM1 = 2 * ((128 + 128) * 144);   // 73728 per CTA
    const int SM2 = 2 * ((128 + 256) * 144);   // 110592
    cudaFuncSetAttribute(k1f, cudaFuncAttributeMaxDynamicSharedMemorySize, SM1);
    cudaFuncSetAttribute(k2f, cudaFuncAttributeMaxDynamicSharedMemorySize, SM2);

    int half = out_size / 2;

    // Fork/join pattern legal under stream capture: s2 must FIRST wait on an
    // event recorded in the capturing stream (fork), then launch, then join.
    cudaStream_t s2;
    cudaStreamCreateWithFlags(&s2, cudaStreamNonBlocking);
    cudaEvent_t evFork, evW;
    cudaEventCreateWithFlags(&evFork, cudaEventDisableTiming);
    cudaEventCreateWithFlags(&evW, cudaEventDisableTiming);

    cudaEventRecord(evFork, 0);           // fork point in capturing stream
    cudaStreamWaitEvent(s2, evFork, 0);   // s2 joins the capture graph

    gather_fp16<<<MT, 256>>>(x, pxs, pys, out + half);          // stream 0
    wtrans<<<(K1 * NN) / 256, 256, 0, s2>>>(W1, K1, w1);        // s2 (overlaps)
    wtrans<<<(NN * NN) / 256, 256, 0, s2>>>(W2, NN, w2);        // s2

    cudaEventRecord(evW, s2);             // join s2 back into stream 0
    cudaStreamWaitEvent(0, evW, 0);

    // signature: (A, B, bias, K, O, W3, b3, Out)
    k1f<<<dim3(MT / 128, 2), 256, SM1>>>(fa, w1, b1, K1,
                                         h1,
                                         (const float*)nullptr,
                                         (const float*)nullptr,
                                         (float*)nullptr);
    k2f<<<dim3(MT / 128, 1), 512, SM2>>>(h1, w2, b2, NN,
                                         (__half*)nullptr,
                                         W3, b3, out);
}